// round 9
// baseline (speedup 1.0000x reference)
#include <cuda_runtime.h>
#include <cuda_bf16.h>

// 16-state Viterbi, 8 carried metrics (tt[s]==tt[s+8]).
// Round 9: R7 (8 lanes/row, lane k owns q[k], 4 rows/warp, 512 single-warp
// blocks, lag-1 decode) with the decode min-tree (3 bfly shfls) replaced by
// ONE segmented redux.sync.min.u32 over order-preserving float->u32 keys
// (sm_100-legal; redux.f32 is not). Key equality == float equality here, so
// the decode rule (min, ballot-eq, lowest-set-bit) is exactly R7's.
// MIO warp-op count drops 6 -> 4 per step. All fp ops bit-identical to the
// verified R7 (rel_err==0).

#define T_LEN 4096
#define B_ROWS 2048
#define NEG_LOG_SQRT_2PI (-0.9189385332046727f)

__device__ __forceinline__ float shfl_idx_raw(float v, int src) {
    float r;
    asm("shfl.sync.idx.b32 %0, %1, %2, 0x1f, 0xffffffff;"
        : "=f"(r) : "f"(v), "r"(src));
    return r;
}
// ballot(a == b) on u32 keys in one asm blob (ISETP + VOTE), full warp
__device__ __forceinline__ unsigned ballot_eq_u32(unsigned a, unsigned b) {
    unsigned r;
    asm("{ .reg .pred p; setp.eq.u32 p, %1, %2;"
        " vote.sync.ballot.b32 %0, p, 0xffffffff; }"
        : "=r"(r) : "r"(a), "r"(b));
    return r;
}
// segmented warp min over this lane's 8-lane group (disjoint masks partition
// the warp; every lane of a group passes the same group mask)
__device__ __forceinline__ unsigned redux_min_u32(unsigned v, unsigned gmask) {
    unsigned r;
    asm("redux.sync.min.u32 %0, %1, %2;" : "=r"(r) : "r"(v), "r"(gmask));
    return r;
}
// order-preserving fp32 -> u32 key (monotone bijection; eq(key) == eq(float))
__device__ __forceinline__ unsigned fkey(float f) {
    unsigned b = __float_as_uint(f);
    return b ^ (unsigned)(((int)b >> 31) | 0x80000000);
}

// Decode parity of the exact first-argmin over the group's key snapshot.
__device__ __forceinline__ float decode8(unsigned ksnap, unsigned gmask, int rowbase) {
    unsigned v = redux_min_u32(ksnap, gmask);     // group min key == min float
    unsigned bal = ballot_eq_u32(ksnap, v);       // one ballot serves all 4 rows
    unsigned seg = bal >> rowbase;                // this row -> low 8 bits
    unsigned lob = seg & (unsigned)(-(int)seg);   // lowest set bit = first argmin
    return (lob & 0xAAu) ? 1.0f : 0.0f;           // parity of its index
}

// One recurrence step: q'[k] = min(q[(2k)&7]+p0, q[(2k+1)&7]+p1).
__device__ __forceinline__ float rec(float q, float p0, float p1,
                                     int src0, int src1) {
    float qs0 = shfl_idx_raw(q, src0);
    float qs1 = shfl_idx_raw(q, src1);
    float m0 = __fadd_rn(qs0, p0);
    float m1 = __fadd_rn(qs1, p1);
    return fminf(m0, m1);
}

// prior for this lane's state: (y - sp)^2 / 2 - C, bit-exact sequence
__device__ __forceinline__ float prior(float yt, float spn) {
    float d = __fadd_rn(yt, spn);
    float t = __fmul_rn(d, d);
    return __fmaf_rn(t, 0.5f, NEG_LOG_SQRT_2PI);
}

__global__ void __launch_bounds__(32, 1)
viterbi8k_kernel(const float* __restrict__ y,
                 const float* __restrict__ h,
                 float* __restrict__ out) {
    int lane    = threadIdx.x & 31;
    int k       = lane & 7;                   // owned metric index 0..7
    int rowbase = lane & ~7;                  // first lane of this row's group
    unsigned gmask = 0xffu << rowbase;        // this row's 8-lane mask
    int row     = blockIdx.x * 4 + (lane >> 3);

    // sp[s] = sum_j (+-1)*h[j], exact products, left-to-right adds; negated.
    float h0 = h[0], h1 = h[1], h2 = h[2], h3 = h[3];
    float spn[2];
#pragma unroll
    for (int t = 0; t < 2; t++) {
        int s = 2 * k + t;                    // this lane's trellis states
        float s3 = ((s >> 3) & 1) ? -1.0f : 1.0f;  // MSB first (shifts 3,2,1,0)
        float s2 = ((s >> 2) & 1) ? -1.0f : 1.0f;
        float s1 = ((s >> 1) & 1) ? -1.0f : 1.0f;
        float s0 = ((s >> 0) & 1) ? -1.0f : 1.0f;
        float sp = __fadd_rn(
                       __fadd_rn(
                           __fadd_rn(__fmul_rn(s3, h0), __fmul_rn(s2, h1)),
                           __fmul_rn(s1, h2)),
                       __fmul_rn(s0, h3));
        spn[t] = -sp;
    }
    float spn0 = spn[0], spn1 = spn[1];

    // shfl source lanes for q[(2k)&7] and q[(2k+1)&7]
    int src0 = rowbase + ((2 * k) & 7);
    int src1 = src0 + 1;

    float q = 0.0f;
    unsigned ka0, kb0, kc0, kd0;              // lag-1 key snapshots
    ka0 = kb0 = kc0 = kd0 = fkey(0.0f);

    const float4* yv = reinterpret_cast<const float4*>(y + (size_t)row * T_LEN);
    float4*       ov = reinterpret_cast<float4*>(out + (size_t)row * T_LEN);

    float4 yy = yv[0];
#pragma unroll 1
    for (int i = 0; i < T_LEN / 4; i++) {
        asm volatile("prefetch.global.L2 [%0];"
                     :: "l"(yv + ((i + 8 < T_LEN / 4) ? i + 8 : i)));
        float4 yn = yv[(i + 1) & (T_LEN / 4 - 1)];   // clamped wrap (in-bounds)

        // priors for this group's 4 steps (independent of q, off-chain)
        float p0x = prior(yy.x, spn0), p1x = prior(yy.x, spn1);
        float p0y = prior(yy.y, spn0), p1y = prior(yy.y, spn1);
        float p0z = prior(yy.z, spn0), p1z = prior(yy.z, spn1);
        float p0w = prior(yy.w, spn0), p1w = prior(yy.w, spn1);

        // decode PREVIOUS group's key snapshots (independent, overlaps recs)
        float4 d;
        d.x = decode8(ka0, gmask, rowbase);
        d.y = decode8(kb0, gmask, rowbase);
        d.z = decode8(kc0, gmask, rowbase);
        d.w = decode8(kd0, gmask, rowbase);

        // recurrence for this group, snapshotting pre-step q as keys
        ka0 = fkey(q); q = rec(q, p0x, p1x, src0, src1);
        kb0 = fkey(q); q = rec(q, p0y, p1y, src0, src1);
        kc0 = fkey(q); q = rec(q, p0z, p1z, src0, src1);
        kd0 = fkey(q); q = rec(q, p0w, p1w, src0, src1);

        if ((k == 0) && (i > 0)) ov[i - 1] = d;  // store lag-1 result
        yy = yn;
    }
    // epilogue: decode + store the final group
    float4 d;
    d.x = decode8(ka0, gmask, rowbase);
    d.y = decode8(kb0, gmask, rowbase);
    d.z = decode8(kc0, gmask, rowbase);
    d.w = decode8(kd0, gmask, rowbase);
    if (k == 0) ov[T_LEN / 4 - 1] = d;
}

extern "C" void kernel_launch(void* const* d_in, const int* in_sizes, int n_in,
                              void* d_out, int out_size) {
    const float* y = (const float*)d_in[0];
    const float* h = (const float*)d_in[1];
    // d_in[2] = transition_table: fixed trellis tt[s] = [2s%16, (2s+1)%16], hardcoded.
    float* out = (float*)d_out;
    viterbi8k_kernel<<<B_ROWS / 4, 32>>>(y, h, out);
}

// round 11
// speedup vs baseline: 4.1356x; 4.1356x over previous
#include <cuda_runtime.h>
#include <cuda_bf16.h>

// 16-state Viterbi, 8 carried metrics (tt[s]==tt[s+8]).
// Round 11 (= Round 10 resubmit; prior bench died to infra, not the kernel):
// R7 core (8 lanes/row, lane k owns q[k], lag-1 decode, bfly+ballot)
// x TWO independent row-batches per warp (rows blk*8+g and blk*8+g+4), so the
// second batch's instructions fill the first batch's latency stalls (in-order
// issue needs independent work). Prior math for the two batches is fused into
// packed f32x2 ops (two independent rn fp32 lanes -> bit-exact per row).
// All per-row fp sequences identical to the verified R7 (rel_err==0).

#define T_LEN 4096
#define B_ROWS 2048
#define NEG_LOG_SQRT_2PI (-0.9189385332046727f)

typedef unsigned long long u64;

__device__ __forceinline__ u64 pk2(float lo, float hi) {
    u64 r; asm("mov.b64 %0, {%1, %2};" : "=l"(r) : "f"(lo), "f"(hi)); return r;
}
__device__ __forceinline__ void upk2(u64 v, float& lo, float& hi) {
    asm("mov.b64 {%0, %1}, %2;" : "=f"(lo), "=f"(hi) : "l"(v));
}
__device__ __forceinline__ u64 add2(u64 a, u64 b) {
    u64 r; asm("add.rn.f32x2 %0, %1, %2;" : "=l"(r) : "l"(a), "l"(b)); return r;
}
__device__ __forceinline__ u64 mul2(u64 a, u64 b) {
    u64 r; asm("mul.rn.f32x2 %0, %1, %2;" : "=l"(r) : "l"(a), "l"(b)); return r;
}
__device__ __forceinline__ u64 fma2(u64 a, u64 b, u64 c) {
    u64 r; asm("fma.rn.f32x2 %0, %1, %2, %3;" : "=l"(r) : "l"(a), "l"(b), "l"(c)); return r;
}
__device__ __forceinline__ float shfl_idx_raw(float v, int src) {
    float r;
    asm("shfl.sync.idx.b32 %0, %1, %2, 0x1f, 0xffffffff;"
        : "=f"(r) : "f"(v), "r"(src));
    return r;
}
__device__ __forceinline__ float shfl_bfly_raw(float v, int mask) {
    float r;
    asm("shfl.sync.bfly.b32 %0, %1, %2, 0x1f, 0xffffffff;"
        : "=f"(r) : "f"(v), "r"(mask));
    return r;
}
__device__ __forceinline__ unsigned ballot_eq_raw(float a, float b) {
    unsigned r;
    asm("{ .reg .pred p; setp.eq.f32 p, %1, %2;"
        " vote.sync.ballot.b32 %0, p, 0xffffffff; }"
        : "=r"(r) : "f"(a), "f"(b));
    return r;
}

// Decode parity of exact first-argmin over the 8-lane group's snapshot (R7).
__device__ __forceinline__ float decode8(float qsnap, int rowbase) {
    float v = qsnap;
    v = fminf(v, shfl_bfly_raw(v, 1));
    v = fminf(v, shfl_bfly_raw(v, 2));
    v = fminf(v, shfl_bfly_raw(v, 4));            // exact group min
    unsigned bal = ballot_eq_raw(qsnap, v);
    unsigned seg = bal >> rowbase;                // this row -> low 8 bits
    unsigned lob = seg & (unsigned)(-(int)seg);   // lowest set bit = first argmin
    return (lob & 0xAAu) ? 1.0f : 0.0f;           // parity of its index
}

// One recurrence step: q'[k] = min(q[(2k)&7]+p0, q[(2k+1)&7]+p1)  (R7).
__device__ __forceinline__ float rec(float q, float p0, float p1,
                                     int src0, int src1) {
    float qs0 = shfl_idx_raw(q, src0);
    float qs1 = shfl_idx_raw(q, src1);
    float m0 = __fadd_rn(qs0, p0);
    float m1 = __fadd_rn(qs1, p1);
    return fminf(m0, m1);
}

// Packed prior for one state, two rows at once: (y - sp)^2/2 - C per lane.
__device__ __forceinline__ void prior2(float ya, float yb, u64 spn_2,
                                       u64 half2, u64 negc2,
                                       float& pa, float& pb) {
    u64 y2 = pk2(ya, yb);
    u64 d  = add2(y2, spn_2);
    u64 t  = mul2(d, d);
    u64 p  = fma2(t, half2, negc2);
    upk2(p, pa, pb);
}

__global__ void __launch_bounds__(32, 1)
viterbi2b_kernel(const float* __restrict__ y,
                 const float* __restrict__ h,
                 float* __restrict__ out) {
    int lane    = threadIdx.x & 31;
    int k       = lane & 7;                   // owned metric index 0..7
    int rowbase = lane & ~7;                  // first lane of this row's group
    int rowA    = blockIdx.x * 8 + (lane >> 3);
    int rowB    = rowA + 4;

    // sp[s] = sum_j (+-1)*h[j], exact products, left-to-right adds; negated.
    float h0 = h[0], h1 = h[1], h2 = h[2], h3 = h[3];
    float spn[2];
#pragma unroll
    for (int t = 0; t < 2; t++) {
        int s = 2 * k + t;                    // this lane's trellis states
        float s3 = ((s >> 3) & 1) ? -1.0f : 1.0f;  // MSB first (shifts 3,2,1,0)
        float s2 = ((s >> 2) & 1) ? -1.0f : 1.0f;
        float s1 = ((s >> 1) & 1) ? -1.0f : 1.0f;
        float s0 = ((s >> 0) & 1) ? -1.0f : 1.0f;
        float sp = __fadd_rn(
                       __fadd_rn(
                           __fadd_rn(__fmul_rn(s3, h0), __fmul_rn(s2, h1)),
                           __fmul_rn(s1, h2)),
                       __fmul_rn(s0, h3));
        spn[t] = -sp;
    }
    u64 spn0_2 = pk2(spn[0], spn[0]);
    u64 spn1_2 = pk2(spn[1], spn[1]);
    u64 half2  = pk2(0.5f, 0.5f);
    u64 negc2  = pk2(NEG_LOG_SQRT_2PI, NEG_LOG_SQRT_2PI);

    int src0 = rowbase + ((2 * k) & 7);       // shfl source for q[(2k)&7]
    int src1 = src0 + 1;

    float qA = 0.0f, qB = 0.0f;
    float aA = 0.0f, bA = 0.0f, cA = 0.0f, dA0 = 0.0f;  // lag-1 snapshots A
    float aB = 0.0f, bB = 0.0f, cB = 0.0f, dB0 = 0.0f;  // lag-1 snapshots B

    const float4* yvA = reinterpret_cast<const float4*>(y + (size_t)rowA * T_LEN);
    const float4* yvB = reinterpret_cast<const float4*>(y + (size_t)rowB * T_LEN);
    float4*       ovA = reinterpret_cast<float4*>(out + (size_t)rowA * T_LEN);
    float4*       ovB = reinterpret_cast<float4*>(out + (size_t)rowB * T_LEN);

    float4 yyA = yvA[0];
    float4 yyB = yvB[0];
#pragma unroll 1
    for (int i = 0; i < T_LEN / 4; i++) {
        int pf = (i + 8 < T_LEN / 4) ? i + 8 : i;
        asm volatile("prefetch.global.L2 [%0];" :: "l"(yvA + pf));
        asm volatile("prefetch.global.L2 [%0];" :: "l"(yvB + pf));
        int nx = (i + 1) & (T_LEN / 4 - 1);           // clamped wrap (in-bounds)
        float4 ynA = yvA[nx];
        float4 ynB = yvB[nx];

        // packed priors: per substep, state 2k and 2k+1, rows A+B fused
        float p0xA, p0xB, p1xA, p1xB, p0yA, p0yB, p1yA, p1yB;
        float p0zA, p0zB, p1zA, p1zB, p0wA, p0wB, p1wA, p1wB;
        prior2(yyA.x, yyB.x, spn0_2, half2, negc2, p0xA, p0xB);
        prior2(yyA.x, yyB.x, spn1_2, half2, negc2, p1xA, p1xB);
        prior2(yyA.y, yyB.y, spn0_2, half2, negc2, p0yA, p0yB);
        prior2(yyA.y, yyB.y, spn1_2, half2, negc2, p1yA, p1yB);
        prior2(yyA.z, yyB.z, spn0_2, half2, negc2, p0zA, p0zB);
        prior2(yyA.z, yyB.z, spn1_2, half2, negc2, p1zA, p1zB);
        prior2(yyA.w, yyB.w, spn0_2, half2, negc2, p0wA, p0wB);
        prior2(yyA.w, yyB.w, spn1_2, half2, negc2, p1wA, p1wB);

        // decode PREVIOUS group's snapshots, both batches (8 indep chains)
        float4 dA, dB;
        dA.x = decode8(aA, rowbase);   dB.x = decode8(aB, rowbase);
        dA.y = decode8(bA, rowbase);   dB.y = decode8(bB, rowbase);
        dA.z = decode8(cA, rowbase);   dB.z = decode8(cB, rowbase);
        dA.w = decode8(dA0, rowbase);  dB.w = decode8(dB0, rowbase);

        // recurrences, interleaved A/B (independent chains)
        aA = qA;  qA = rec(qA, p0xA, p1xA, src0, src1);
        aB = qB;  qB = rec(qB, p0xB, p1xB, src0, src1);
        bA = qA;  qA = rec(qA, p0yA, p1yA, src0, src1);
        bB = qB;  qB = rec(qB, p0yB, p1yB, src0, src1);
        cA = qA;  qA = rec(qA, p0zA, p1zA, src0, src1);
        cB = qB;  qB = rec(qB, p0zB, p1zB, src0, src1);
        dA0 = qA; qA = rec(qA, p0wA, p1wA, src0, src1);
        dB0 = qB; qB = rec(qB, p0wB, p1wB, src0, src1);

        if ((k == 0) && (i > 0)) {
            ovA[i - 1] = dA;
            ovB[i - 1] = dB;
        }
        yyA = ynA;
        yyB = ynB;
    }
    // epilogue: decode + store the final group, both batches
    float4 dA, dB;
    dA.x = decode8(aA, rowbase);   dB.x = decode8(aB, rowbase);
    dA.y = decode8(bA, rowbase);   dB.y = decode8(bB, rowbase);
    dA.z = decode8(cA, rowbase);   dB.z = decode8(cB, rowbase);
    dA.w = decode8(dA0, rowbase);  dB.w = decode8(dB0, rowbase);
    if (k == 0) {
        ovA[T_LEN / 4 - 1] = dA;
        ovB[T_LEN / 4 - 1] = dB;
    }
}

extern "C" void kernel_launch(void* const* d_in, const int* in_sizes, int n_in,
                              void* d_out, int out_size) {
    const float* y = (const float*)d_in[0];
    const float* h = (const float*)d_in[1];
    // d_in[2] = transition_table: fixed trellis tt[s] = [2s%16, (2s+1)%16], hardcoded.
    float* out = (float*)d_out;
    viterbi2b_kernel<<<B_ROWS / 8, 32>>>(y, h, out);
}

// round 14
// speedup vs baseline: 5.0044x; 1.2101x over previous
#include <cuda_runtime.h>
#include <cuda_bf16.h>

// 16-state Viterbi, 8 carried metrics (tt[s]==tt[s+8]).
// Round 14 (= R12 design, exchange shuffles switched from raw inline-PTX to
// the proven __shfl_xor_sync intrinsic after two container failures):
// 2 lanes per row (even lane owns q0..3, odd q4..7), 16 rows/warp,
// 128 single-warp blocks. Per step: 4 xor-shfls exchange the quads so EVERY
// lane holds all 8 metrics; butterfly update is local packed f32x2; the
// argmin decode is pure local ALU (verified R2 tree), parity-split so each
// lane decodes 2 of the 4 substeps and stores its own float2.
// Collective ops/step = 4 (R7 had 6, R11 12) -- per-warp collective-op floor.
// All fp sequences bit-identical to the verified R2/R7 (rel_err==0).

#define T_LEN 4096
#define B_ROWS 2048
#define NEG_LOG_SQRT_2PI (-0.9189385332046727f)

typedef unsigned long long u64;

__device__ __forceinline__ u64 pk2(float lo, float hi) {
    u64 r; asm("mov.b64 %0, {%1, %2};" : "=l"(r) : "f"(lo), "f"(hi)); return r;
}
__device__ __forceinline__ void upk2(u64 v, float& lo, float& hi) {
    asm("mov.b64 {%0, %1}, %2;" : "=f"(lo), "=f"(hi) : "l"(v));
}
__device__ __forceinline__ u64 add2(u64 a, u64 b) {
    u64 r; asm("add.rn.f32x2 %0, %1, %2;" : "=l"(r) : "l"(a), "l"(b)); return r;
}
__device__ __forceinline__ u64 mul2(u64 a, u64 b) {
    u64 r; asm("mul.rn.f32x2 %0, %1, %2;" : "=l"(r) : "l"(a), "l"(b)); return r;
}
__device__ __forceinline__ u64 fma2(u64 a, u64 b, u64 c) {
    u64 r; asm("fma.rn.f32x2 %0, %1, %2, %3;" : "=l"(r) : "l"(a), "l"(b), "l"(c)); return r;
}
__device__ __forceinline__ float shflx(float v) {
    return __shfl_xor_sync(0xffffffffu, v, 1, 32);   // proven path (R4/R5)
}

// Verified R2 decode tree: parity of exact first-argmin (left priority).
__device__ __forceinline__ float dec8(u64 C01, u64 C23, u64 C45, u64 C67) {
    float q0, q1, q2, q3, q4, q5, q6, q7;
    upk2(C01, q0, q1); upk2(C23, q2, q3);
    upk2(C45, q4, q5); upk2(C67, q6, q7);
    float p01 = (q1 < q0) ? 1.0f : 0.0f;  float v01 = fminf(q0, q1);
    float p23 = (q3 < q2) ? 1.0f : 0.0f;  float v23 = fminf(q2, q3);
    float p45 = (q5 < q4) ? 1.0f : 0.0f;  float v45 = fminf(q4, q5);
    float p67 = (q7 < q6) ? 1.0f : 0.0f;  float v67 = fminf(q6, q7);
    float pa  = (v23 < v01) ? p23 : p01;  float va  = fminf(v01, v23);
    float pb  = (v67 < v45) ? p67 : p45;  float vb  = fminf(v45, v67);
    return (vb < va) ? pb : pa;
}

// One trellis step. qpA/qpB = this lane's owned metric pairs
// (even: (q0,q1),(q2,q3); odd: (q4,q5),(q6,q7)). sA..sD = packed -sp for this
// lane's destination m-range [8h..8h+7]. Exports the canonical PRE-step
// metric set C01..C67 (q0..q7) for the decoder.
__device__ __forceinline__ void vstep(u64& qpA, u64& qpB,
                                      u64 sA, u64 sB, u64 sC, u64 sD,
                                      u64 half2, u64 negc2, bool evn, float yt,
                                      u64& C01, u64& C23, u64& C45, u64& C67) {
    // priors for this lane's 8 destination m's (off the carried chain)
    u64 y2 = pk2(yt, yt);
    u64 dA = add2(y2, sA); u64 tA = mul2(dA, dA); u64 prA = fma2(tA, half2, negc2);
    u64 dB = add2(y2, sB); u64 tB = mul2(dB, dB); u64 prB = fma2(tB, half2, negc2);
    u64 dC = add2(y2, sC); u64 tC = mul2(dC, dC); u64 prC = fma2(tC, half2, negc2);
    u64 dD = add2(y2, sD); u64 tD = mul2(dD, dD); u64 prD = fma2(tD, half2, negc2);

    // exchange: full quad swap with the partner lane (4 b32 xor shfls)
    float a0, a1, b0, b1;
    upk2(qpA, a0, a1); upk2(qpB, b0, b1);
    float r0 = shflx(a0);
    float r1 = shflx(a1);
    float r2 = shflx(b0);
    float r3 = shflx(b1);
    u64 rq01 = pk2(r0, r1);
    u64 rq23 = pk2(r2, r3);

    // canonical ordered metric set q0..q7 (pre-step), both lanes identical
    C01 = evn ? qpA : rq01;
    C23 = evn ? qpB : rq23;
    C45 = evn ? rq01 : qpA;
    C67 = evn ? rq23 : qpB;

    // m[8h+j] = q[j] + pr[8h+j]; out[4h+t] = min(m[8h+2t], m[8h+2t+1])
    u64 mA = add2(C01, prA);
    u64 mB = add2(C23, prB);
    u64 mC = add2(C45, prC);
    u64 mD = add2(C67, prD);
    float x0, x1;
    upk2(mA, x0, x1); float oa = fminf(x0, x1);
    upk2(mB, x0, x1); float ob = fminf(x0, x1);
    upk2(mC, x0, x1); float oc = fminf(x0, x1);
    upk2(mD, x0, x1); float od = fminf(x0, x1);
    qpA = pk2(oa, ob);   // even: (out0,out1) | odd: (out4,out5)
    qpB = pk2(oc, od);   // even: (out2,out3) | odd: (out6,out7)
}

__global__ void __launch_bounds__(32, 1)
viterbi2li_kernel(const float* __restrict__ y,
                  const float* __restrict__ h,
                  float* __restrict__ out) {
    int lane = threadIdx.x & 31;
    int hb   = lane & 1;                       // 0: owns q0..3, 1: owns q4..7
    bool evn = (hb == 0);
    int row  = blockIdx.x * 16 + (lane >> 1);

    // sp[s] = sum_j (+-1)*h[j], exact products, left-to-right adds; negated.
    float h0 = h[0], h1 = h[1], h2 = h[2], h3 = h[3];
    float spn[16];
#pragma unroll
    for (int s = 0; s < 16; s++) {
        float s3 = ((s >> 3) & 1) ? -1.0f : 1.0f;  // MSB first (shifts 3,2,1,0)
        float s2 = ((s >> 2) & 1) ? -1.0f : 1.0f;
        float s1 = ((s >> 1) & 1) ? -1.0f : 1.0f;
        float s0 = ((s >> 0) & 1) ? -1.0f : 1.0f;
        float sp = __fadd_rn(
                       __fadd_rn(
                           __fadd_rn(__fmul_rn(s3, h0), __fmul_rn(s2, h1)),
                           __fmul_rn(s1, h2)),
                       __fmul_rn(s0, h3));
        spn[s] = -sp;
    }
    // this lane's destination m-range is [8h .. 8h+7]
    int mb = hb * 8;
    u64 sA = pk2(spn[mb + 0], spn[mb + 1]);
    u64 sB = pk2(spn[mb + 2], spn[mb + 3]);
    u64 sC = pk2(spn[mb + 4], spn[mb + 5]);
    u64 sD = pk2(spn[mb + 6], spn[mb + 7]);
    u64 half2 = pk2(0.5f, 0.5f);
    u64 negc2 = pk2(NEG_LOG_SQRT_2PI, NEG_LOG_SQRT_2PI);

    u64 qpA = 0ull;  // (+0, +0)
    u64 qpB = 0ull;

    const float4* yv = reinterpret_cast<const float4*>(y + (size_t)row * T_LEN);
    float2*       ov = reinterpret_cast<float2*>(out + (size_t)row * T_LEN);

    float4 yy = yv[0];                         // both lanes: same addr (bcast)
#pragma unroll 1
    for (int i = 0; i < T_LEN / 4; i++) {
        asm volatile("prefetch.global.L2 [%0];"
                     :: "l"(yv + ((i + 8 < T_LEN / 4) ? i + 8 : i)));
        float4 yn = yv[(i + 1) & (T_LEN / 4 - 1)];   // clamped wrap (in-bounds)

        u64 C01_0, C23_0, C45_0, C67_0;
        u64 C01_1, C23_1, C45_1, C67_1;
        u64 C01_2, C23_2, C45_2, C67_2;
        u64 C01_3, C23_3, C45_3, C67_3;
        vstep(qpA, qpB, sA, sB, sC, sD, half2, negc2, evn, yy.x,
              C01_0, C23_0, C45_0, C67_0);
        vstep(qpA, qpB, sA, sB, sC, sD, half2, negc2, evn, yy.y,
              C01_1, C23_1, C45_1, C67_1);
        vstep(qpA, qpB, sA, sB, sC, sD, half2, negc2, evn, yy.z,
              C01_2, C23_2, C45_2, C67_2);
        vstep(qpA, qpB, sA, sB, sC, sD, half2, negc2, evn, yy.w,
              C01_3, C23_3, C45_3, C67_3);

        // parity-split decode: even lanes decode substeps 0,1; odd 2,3.
        u64 E01a = evn ? C01_0 : C01_2, E23a = evn ? C23_0 : C23_2;
        u64 E45a = evn ? C45_0 : C45_2, E67a = evn ? C67_0 : C67_2;
        u64 E01b = evn ? C01_1 : C01_3, E23b = evn ? C23_1 : C23_3;
        u64 E45b = evn ? C45_1 : C45_3, E67b = evn ? C67_1 : C67_3;
        float f0 = dec8(E01a, E23a, E45a, E67a);
        float f1 = dec8(E01b, E23b, E45b, E67b);

        ov[2 * i + hb] = make_float2(f0, f1);  // even: t0,t1 | odd: t2,t3
        yy = yn;
    }
}

extern "C" void kernel_launch(void* const* d_in, const int* in_sizes, int n_in,
                              void* d_out, int out_size) {
    const float* y = (const float*)d_in[0];
    const float* h = (const float*)d_in[1];
    // d_in[2] = transition_table: fixed trellis tt[s] = [2s%16, (2s+1)%16], hardcoded.
    float* out = (float*)d_out;
    viterbi2li_kernel<<<B_ROWS / 16, 32>>>(y, h, out);
}

// round 15
// speedup vs baseline: 6.2823x; 1.2554x over previous
#include <cuda_runtime.h>
#include <cuda_bf16.h>

// 16-state Viterbi, 8 carried metrics (tt[s]==tt[s+8]).
// Round 15: R7 skeleton (8 lanes/row, lane k owns q[k], 4 rows/warp, 512
// single-warp blocks, lag-1 decode) but the decode moves from warp shuffles
// to SHARED MEMORY: each substep every lane stores its pre-step q[k] into a
// double-buffered smem ring (conflict-free STS.32); next iteration 16 lanes
// each read one (row,substep) 8-metric snapshot (2x LDS.128) and run the
// verified local argmin tree (pure ALU, exact first-index).
// Warp-collective ops drop 6 -> 2 per step; decode leaves the SB-slot pool.
// All fp sequences bit-identical to the verified R1/R2/R7 (rel_err==0).

#define T_LEN 4096
#define B_ROWS 2048
#define NEG_LOG_SQRT_2PI (-0.9189385332046727f)

__device__ __forceinline__ float shfl_idx_raw(float v, int src) {
    float r;
    asm("shfl.sync.idx.b32 %0, %1, %2, 0x1f, 0xffffffff;"
        : "=f"(r) : "f"(v), "r"(src));
    return r;
}

// One recurrence step: q'[k] = min(q[(2k)&7]+p0, q[(2k+1)&7]+p1)  (R7).
__device__ __forceinline__ float rec(float q, float p0, float p1,
                                     int src0, int src1) {
    float qs0 = shfl_idx_raw(q, src0);
    float qs1 = shfl_idx_raw(q, src1);
    float m0 = __fadd_rn(qs0, p0);
    float m1 = __fadd_rn(qs1, p1);
    return fminf(m0, m1);
}

// prior for this lane's state: (y - sp)^2 / 2 - C, bit-exact sequence (R7)
__device__ __forceinline__ float prior(float yt, float spn) {
    float d = __fadd_rn(yt, spn);
    float t = __fmul_rn(d, d);
    return __fmaf_rn(t, 0.5f, NEG_LOG_SQRT_2PI);
}

// Verified local decode tree (R1/R2): parity of exact first-argmin
// (left-priority strict-< == jnp.argmin first-index semantics).
__device__ __forceinline__ float dec8(float4 lo, float4 hi) {
    float p01 = (lo.y < lo.x) ? 1.0f : 0.0f;  float v01 = fminf(lo.x, lo.y);
    float p23 = (lo.w < lo.z) ? 1.0f : 0.0f;  float v23 = fminf(lo.z, lo.w);
    float p45 = (hi.y < hi.x) ? 1.0f : 0.0f;  float v45 = fminf(hi.x, hi.y);
    float p67 = (hi.w < hi.z) ? 1.0f : 0.0f;  float v67 = fminf(hi.z, hi.w);
    float pa  = (v23 < v01) ? p23 : p01;      float va  = fminf(v01, v23);
    float pb  = (v67 < v45) ? p67 : p45;      float vb  = fminf(v45, v67);
    return (vb < va) ? pb : pa;
}

// smem ring: [buf(2)][sub(4) stride 36 words][rw(4) stride 8][k(8)]
// STS word index = buf*144 + sub*36 + lane  (lane = rw*8+k) -> conflict-free.
// LDS.128 base  = buf*144 + sub*36 + rw*8   (16B aligned: 576/144/32 bytes).
#define SQ_BUF 144

__global__ void __launch_bounds__(32, 1)
viterbi_sm_kernel(const float* __restrict__ y,
                  const float* __restrict__ h,
                  float* __restrict__ out) {
    __shared__ __align__(16) float sq[2 * SQ_BUF];

    int lane = threadIdx.x & 31;
    int k    = lane & 7;                      // owned metric index 0..7
    int rw   = lane >> 3;                     // row-in-warp 0..3
    int row  = blockIdx.x * 4 + rw;

    // sp[s] = sum_j (+-1)*h[j], exact products, left-to-right adds; negated.
    float h0 = h[0], h1 = h[1], h2 = h[2], h3 = h[3];
    float spn[2];
#pragma unroll
    for (int t = 0; t < 2; t++) {
        int s = 2 * k + t;                    // this lane's trellis states
        float s3 = ((s >> 3) & 1) ? -1.0f : 1.0f;  // MSB first (shifts 3,2,1,0)
        float s2 = ((s >> 2) & 1) ? -1.0f : 1.0f;
        float s1 = ((s >> 1) & 1) ? -1.0f : 1.0f;
        float s0 = ((s >> 0) & 1) ? -1.0f : 1.0f;
        float sp = __fadd_rn(
                       __fadd_rn(
                           __fadd_rn(__fmul_rn(s3, h0), __fmul_rn(s2, h1)),
                           __fmul_rn(s1, h2)),
                       __fmul_rn(s0, h3));
        spn[t] = -sp;
    }
    float spn0 = spn[0], spn1 = spn[1];

    int src0 = (lane & ~7) + ((2 * k) & 7);   // shfl source for q[(2k)&7]
    int src1 = src0 + 1;

    // decode role (all 32 lanes compute; only lanes 0..15 store)
    int dsub = lane & 3;                      // substep this lane decodes
    int drw  = (lane >> 2) & 3;               // row-in-warp this lane decodes
    int drow = blockIdx.x * 4 + drw;

    float q = 0.0f;

    const float4* yv = reinterpret_cast<const float4*>(y + (size_t)row * T_LEN);

    float4 yy = yv[0];                        // 8 lanes/row: broadcast load
#pragma unroll 1
    for (int i = 0; i < T_LEN / 4; i++) {
        __syncwarp();                         // iter i-1 STS visible to LDS
        asm volatile("prefetch.global.L2 [%0];"
                     :: "l"(yv + ((i + 8 < T_LEN / 4) ? i + 8 : i)));
        float4 yn = yv[(i + 1) & (T_LEN / 4 - 1)];   // clamped wrap (in-bounds)

        int buf  = (i & 1) * SQ_BUF;
        int pbuf = SQ_BUF - buf;              // previous buffer

        // decode previous group's snapshots (local ALU, lag-hidden LDS)
        int doff = pbuf + dsub * 36 + drw * 8;
        float4 qlo = *reinterpret_cast<const float4*>(&sq[doff]);
        float4 qhi = *reinterpret_cast<const float4*>(&sq[doff + 4]);
        float par = dec8(qlo, qhi);

        // priors for this group's 4 steps (independent of q, off-chain)
        float p0x = prior(yy.x, spn0), p1x = prior(yy.x, spn1);
        float p0y = prior(yy.y, spn0), p1y = prior(yy.y, spn1);
        float p0z = prior(yy.z, spn0), p1z = prior(yy.z, spn1);
        float p0w = prior(yy.w, spn0), p1w = prior(yy.w, spn1);

        // recurrence, snapshotting pre-step q into smem (conflict-free STS)
        sq[buf + 0 * 36 + lane] = q;  q = rec(q, p0x, p1x, src0, src1);
        sq[buf + 1 * 36 + lane] = q;  q = rec(q, p0y, p1y, src0, src1);
        sq[buf + 2 * 36 + lane] = q;  q = rec(q, p0z, p1z, src0, src1);
        sq[buf + 3 * 36 + lane] = q;  q = rec(q, p0w, p1w, src0, src1);

        if ((lane < 16) && (i > 0))
            out[(size_t)drow * T_LEN + 4 * (i - 1) + dsub] = par;
        yy = yn;
    }
    // epilogue: decode + store the final group (written to buf = SQ_BUF)
    __syncwarp();
    int doff = SQ_BUF + dsub * 36 + drw * 8;
    float4 qlo = *reinterpret_cast<const float4*>(&sq[doff]);
    float4 qhi = *reinterpret_cast<const float4*>(&sq[doff + 4]);
    float par = dec8(qlo, qhi);
    if (lane < 16)
        out[(size_t)drow * T_LEN + 4 * (T_LEN / 4 - 1) + dsub] = par;
}

extern "C" void kernel_launch(void* const* d_in, const int* in_sizes, int n_in,
                              void* d_out, int out_size) {
    const float* y = (const float*)d_in[0];
    const float* h = (const float*)d_in[1];
    // d_in[2] = transition_table: fixed trellis tt[s] = [2s%16, (2s+1)%16], hardcoded.
    float* out = (float*)d_out;
    viterbi_sm_kernel<<<B_ROWS / 4, 32>>>(y, h, out);
}